// round 1
// baseline (speedup 1.0000x reference)
#include <cuda_runtime.h>
#include <math.h>

#define NTT 730
#define NSS 2000
#define NHH 16
#define NRR 15
#define NSH (NSS*NHH)          // 32000
#define NTS (NTT*NSS)          // 1460000

// -------- scratch (device globals; no allocation) --------
__device__ __align__(128) float g_base1[256*NSS];
__device__ __align__(128) float g_base2[256*NSS];
__device__ __align__(128) float g_k1[NSH], g_k2[NSH], g_k23[NSH], g_k3[NSH];
__device__ __align__(128) float g_gl[NSH], g_qb[NSH], g_ge1[NSH], g_ge2[NSH];
__device__ __align__(128) float g_cw[NSH*NRR];
__device__ __align__(128) float g_vi[(size_t)NTT*NSH];
__device__ __align__(128) float g_vk[(size_t)NTT*NSH];
__device__ __align__(128) float g_vm[(size_t)NTT*NSH];
__device__ __align__(128) float g_Ps[NTS], g_Pl[NTS], g_E[NTS];
__device__ __align__(128) float g_QT[(size_t)NTT*NSH];

__device__ __forceinline__ float tanh_fast(float x) {
    float e = __expf(2.f * x);
    return 1.f - __fdividef(2.f, e + 1.f);   // -> -1 / +1 at extremes, err ~1e-7
}
__device__ __forceinline__ float sigmoid_f(float x) {
    return __fdividef(1.f, 1.f + __expf(-x));
}
__device__ __forceinline__ float hsig(float x) {
    return __saturatef(x * (1.f/6.f) + 0.5f);
}

// =====================================================================
// Kernel A: per-basin MLPs (w, wR) + precomputed bases for v1/v2
// grid = NSS blocks x 256 threads
// =====================================================================
__global__ __launch_bounds__(256) void prep_kernel(
    const float* __restrict__ xc,
    const float* __restrict__ fc_W1,  const float* __restrict__ fc_b1,
    const float* __restrict__ fc_W2,  const float* __restrict__ fc_b2,
    const float* __restrict__ fcR_W1, const float* __restrict__ fcR_b1,
    const float* __restrict__ fcR_W2, const float* __restrict__ fcR_b2,
    const float* __restrict__ fcT1_W1,const float* __restrict__ fcT1_b1,
    const float* __restrict__ fcT2_W1,const float* __restrict__ fcT2_b1)
{
    int s = blockIdx.x;
    int tid = threadIdx.x;
    __shared__ float sxc[32];
    __shared__ float sh_h[256], sh_hR[256];
    __shared__ float sh_w[160], sh_wR[240];
    __shared__ float sh_ga[16];

    if (tid < 32) sxc[tid] = xc[s*32 + tid];
    __syncthreads();

    {   // hidden layers + bases (thread = hidden unit k)
        int k = tid;
        float a0 = fc_b1[k], a1 = fcR_b1[k], a2 = fcT1_b1[k], a3 = fcT2_b1[k];
        #pragma unroll
        for (int g = 0; g < 32; g++) {
            float xg = sxc[g];
            a0 += xg * fc_W1 [k*32 + g];
            a1 += xg * fcR_W1[k*32 + g];
            a2 += xg * fcT1_W1[k*33 + 1 + g];
            a3 += xg * fcT2_W1[k*35 + 3 + g];
        }
        sh_h[k]  = tanh_fast(a0);
        sh_hR[k] = tanh_fast(a1);
        g_base1[k*NSS + s] = a2;   // pre-tanh; LAI term added later
        g_base2[k*NSS + s] = a3;
    }
    __syncthreads();

    // output layers: 160 (w) + 240 (wR), warp-per-output
    int warp = tid >> 5, lane = tid & 31;
    for (int o = warp; o < 400; o += 8) {
        float sum = 0.f;
        if (o < 160) {
            const float* w = fc_W2 + o*256;
            for (int k = lane; k < 256; k += 32) sum += sh_h[k] * w[k];
        } else {
            const float* w = fcR_W2 + (o-160)*256;
            for (int k = lane; k < 256; k += 32) sum += sh_hR[k] * w[k];
        }
        #pragma unroll
        for (int off = 16; off; off >>= 1) sum += __shfl_down_sync(0xffffffffu, sum, off);
        if (lane == 0) {
            if (o < 160) sh_w[o] = sum + fc_b2[o];
            else         sh_wR[o-160] = sum + fcR_b2[o-160];
        }
    }
    __syncthreads();

    if (tid < 16) {
        int h = tid, g = s*16 + h;
        g_k1 [g] = sigmoid_f(sh_w[ 16 + h]);
        g_k2 [g] = sigmoid_f(sh_w[ 32 + h]);
        g_k23[g] = sigmoid_f(sh_w[ 48 + h]);
        g_k3 [g] = sigmoid_f(sh_w[ 64 + h]) * 0.1f;
        g_gl [g] = __expf(sh_w[ 80 + h]) * 2.f;
        g_qb [g] = fmaxf(sh_w[112 + h], 0.f);
        g_ge1[g] = fmaxf(sh_w[128 + h], 0.f);
        g_ge2[g] = fmaxf(sh_w[144 + h], 0.f);
        // softmax over the 16 heads
        float m = -1e30f;
        #pragma unroll
        for (int j = 0; j < 16; j++) m = fmaxf(m, sh_w[96 + j]);
        float den = 0.f;
        #pragma unroll
        for (int j = 0; j < 16; j++) den += __expf(sh_w[96 + j] - m);
        sh_ga[h] = __fdividef(__expf(sh_w[96 + h] - m), den);
    }
    __syncthreads();

    // conv weights folded with ga, kernel-index flipped for causal form
    if (tid < 240) {
        int h = tid / 15, d = tid - h*15;
        g_cw[(s*16 + h)*15 + d] = sh_ga[h] * fmaxf(sh_wR[h*15 + (14 - d)], 0.f);
    }
}

// =====================================================================
// Kernel B: fused per-(t,s) MLPs  ->  vi, vk, vm  (+ Ps, Pl, E)
// block = 256 threads = 8 warps; warp = one t, lanes = 32 basins
// =====================================================================
#define TPASS 8
#define TCHUNK 32
#define SMEM_B_FLOATS (256*32*2 + 256*4 + 256*48 + 48)
#define SMEM_B_BYTES (SMEM_B_FLOATS*4)

__global__ __launch_bounds__(256) void mlp_kernel(
    const float* __restrict__ x,
    const float* __restrict__ fcT1_W1, const float* __restrict__ fcT2_W1,
    const float* __restrict__ fcT1_W2, const float* __restrict__ fcT1_b2,
    const float* __restrict__ fcT2_W2, const float* __restrict__ fcT2_b2)
{
    extern __shared__ float smem[];
    float*  sb1   = smem;                       // [256][32]
    float*  sb2   = sb1 + 256*32;               // [256][32]
    float4* swc   = (float4*)(sb2 + 256*32);    // [256] {c_LAI, c_R, c_T1, c_T2}
    float*  sw2   = (float*)(swc + 256);        // [256][48]  (k-major)
    float*  sbias = sw2 + 256*48;               // [48]

    int tid = threadIdx.x;
    int s0 = blockIdx.y * 32;
    int t0 = blockIdx.x * TCHUNK;

    for (int i = tid; i < 256*32; i += 256) {
        int k = i >> 5, j = i & 31;
        int s = s0 + j;
        float v1 = 0.f, v2 = 0.f;
        if (s < NSS) { v1 = g_base1[k*NSS + s]; v2 = g_base2[k*NSS + s]; }
        sb1[i] = v1; sb2[i] = v2;
    }
    swc[tid] = make_float4(fcT1_W1[tid*33], fcT2_W1[tid*35],
                           fcT2_W1[tid*35 + 1], fcT2_W1[tid*35 + 2]);
    for (int i = tid; i < 256*48; i += 256) {
        int k = i / 48, o = i - k*48;
        sw2[i] = (o < 32) ? fcT1_W2[o*256 + k] : fcT2_W2[(o-32)*256 + k];
    }
    if (tid < 48) sbias[tid] = (tid < 32) ? fcT1_b2[tid] : fcT2_b2[tid - 32];
    __syncthreads();

    int lane = tid & 31, warp = tid >> 5;
    int s = s0 + lane;

    for (int p = 0; p < TCHUNK/TPASS; p++) {
        int t = t0 + p*TPASS + warp;
        if (t >= NTT || s >= NSS) continue;

        const float* xe = x + (size_t)(t*NSS + s)*6;
        float P = xe[0], E = xe[1], T1v = xe[2], T2v = xe[3], Rv = xe[4], LAI = xe[5];

        // snow/rain partition vp
        float denom = T2v - T1v;
        float ratio = (T1v + T2v) / (denom == 0.f ? 1.f : denom);
        ratio = fminf(fmaxf(ratio, -1.f), 1.f);
        if ((T1v >= 0.f) || (T2v <= 0.f)) ratio = 0.f;
        float vp = 1.f - acosf(ratio) / 3.1415f;
        if (T1v >= 0.f) vp = 1.f;
        if (T2v <= 0.f) vp = 0.f;
        int ts = t*NSS + s;
        g_Ps[ts] = P * (1.f - vp);
        g_Pl[ts] = P * vp;
        g_E[ts]  = E;

        float acc[48];
        #pragma unroll
        for (int o = 0; o < 48; o++) acc[o] = 0.f;

        #pragma unroll 2
        for (int k = 0; k < 256; k++) {
            float4 wc = swc[k];
            float h1 = tanh_fast(sb1[(k<<5) + lane] + LAI*wc.x);
            float h2 = tanh_fast(sb2[(k<<5) + lane] + Rv*wc.y + T1v*wc.z + T2v*wc.w);
            const float4* wv = (const float4*)(sw2 + k*48);
            #pragma unroll
            for (int q = 0; q < 8; q++) {
                float4 w4 = wv[q];
                acc[4*q+0] += w4.x * h1;
                acc[4*q+1] += w4.y * h1;
                acc[4*q+2] += w4.z * h1;
                acc[4*q+3] += w4.w * h1;
            }
            #pragma unroll
            for (int q = 8; q < 12; q++) {
                float4 w4 = wv[q];
                acc[4*q+0] += w4.x * h2;
                acc[4*q+1] += w4.y * h2;
                acc[4*q+2] += w4.z * h2;
                acc[4*q+3] += w4.w * h2;
            }
        }

        size_t base = (size_t)t*NSH + s*16;
        #pragma unroll
        for (int q = 0; q < 4; q++) {
            float4 a;
            a.x = hsig(acc[4*q+0] + sbias[4*q+0]);
            a.y = hsig(acc[4*q+1] + sbias[4*q+1]);
            a.z = hsig(acc[4*q+2] + sbias[4*q+2]);
            a.w = hsig(acc[4*q+3] + sbias[4*q+3]);
            *(float4*)(g_vi + base + 4*q) = a;
            float4 b;
            b.x = hsig(acc[16+4*q+0] + sbias[16+4*q+0]);
            b.y = hsig(acc[16+4*q+1] + sbias[16+4*q+1]);
            b.z = hsig(acc[16+4*q+2] + sbias[16+4*q+2]);
            b.w = hsig(acc[16+4*q+3] + sbias[16+4*q+3]);
            *(float4*)(g_vk + base + 4*q) = b;
            float4 c;
            c.x = __expf(2.f*(acc[32+4*q+0] + sbias[32+4*q+0]));
            c.y = __expf(2.f*(acc[32+4*q+1] + sbias[32+4*q+1]));
            c.z = __expf(2.f*(acc[32+4*q+2] + sbias[32+4*q+2]));
            c.w = __expf(2.f*(acc[32+4*q+3] + sbias[32+4*q+3]));
            *(float4*)(g_vm + base + 4*q) = c;
        }
    }
}

// =====================================================================
// Kernel C: sequential reservoir scan; thread = (s,h), writes Q1+Q2+Q3
// =====================================================================
__global__ __launch_bounds__(128) void scan_kernel()
{
    int g = blockIdx.x * 128 + threadIdx.x;
    if (g >= NSH) return;
    int s = g >> 4;
    float k1 = g_k1[g], k2 = g_k2[g], k23 = g_k23[g], k3 = g_k3[g];
    float gl = g_gl[g], qb = g_qb[g], ge1 = g_ge1[g], ge2 = g_ge2[g];
    float S0 = 0.f, Sv = 0.f, S2 = 0.f, S3 = 0.f;

    #pragma unroll 2
    for (int t = 0; t < NTT; t++) {
        int ts = t*NSS + s;
        size_t tg = (size_t)t*NSH + g;
        float Ps = g_Ps[ts], Pl = g_Pl[ts], E = g_E[ts];
        float vi = g_vi[tg], vk = g_vk[tg], vm = g_vm[tg];

        float H0  = S0 + Ps;
        float qSm = fminf(H0, vm);
        float Hv  = fmaxf(Sv + Pl*(1.f - vi) - E*ge1, 0.f);
        float qv  = Sv * vk;
        float H2  = fmaxf(S2 + qSm + qv - E*ge2 + Pl*vi, 0.f);
        float x1  = H2 - gl;
        float Q1  = (x1 > 0.f) ? exp2f(k1 * __log2f(x1)) : 0.f;
        float q2  = fminf(H2, gl) * k2;
        float Q2  = q2 * (1.f - k23);
        float H3  = S3 + q2 * k23;
        float Q3  = H3 * k3 + qb;

        S0 = H0 - qSm;
        Sv = Hv - qv;
        S2 = H2 - Q1 - q2;
        S3 = H3 - Q3;
        g_QT[tg] = Q1 + Q2 + Q3;
    }
}

// =====================================================================
// Kernel D: causal depthwise conv (ga folded into weights) + head-sum
// block: one basin x 128 timesteps
// =====================================================================
#define CTT 128
__global__ __launch_bounds__(128) void conv_kernel(float* __restrict__ out)
{
    __shared__ float shQ[16*(CTT+16)];     // stride 144, conflict-free reads
    __shared__ float shc[NHH*NRR];         // 240
    int s = blockIdx.y;
    int t0 = blockIdx.x * CTT;
    int tid = threadIdx.x;

    for (int i = tid; i < 16*(CTT+14); i += 128) {
        int j = i >> 4, h = i & 15;
        int t = t0 - 14 + j;
        shQ[h*(CTT+16) + j] = (t >= 0 && t < NTT)
            ? g_QT[(size_t)t*NSH + s*16 + h] : 0.f;
    }
    for (int i = tid; i < 240; i += 128) shc[i] = g_cw[s*240 + i];
    __syncthreads();

    int t = t0 + tid;
    if (t < NTT) {
        float acc = 0.f;
        #pragma unroll
        for (int h = 0; h < 16; h++) {
            const float* q = shQ + h*(CTT+16) + tid;
            #pragma unroll
            for (int d = 0; d < 15; d++)
                acc += q[14 - d] * shc[h*15 + d];
        }
        out[t*NSS + s] = acc;
    }
}

// =====================================================================
extern "C" void kernel_launch(void* const* d_in, const int* in_sizes, int n_in,
                              void* d_out, int out_size)
{
    const float* x       = (const float*)d_in[0];
    const float* xc      = (const float*)d_in[1];
    const float* fc_W1   = (const float*)d_in[2];
    const float* fc_b1   = (const float*)d_in[3];
    const float* fc_W2   = (const float*)d_in[4];
    const float* fc_b2   = (const float*)d_in[5];
    const float* fcR_W1  = (const float*)d_in[6];
    const float* fcR_b1  = (const float*)d_in[7];
    const float* fcR_W2  = (const float*)d_in[8];
    const float* fcR_b2  = (const float*)d_in[9];
    const float* fcT1_W1 = (const float*)d_in[10];
    const float* fcT1_b1 = (const float*)d_in[11];
    const float* fcT1_W2 = (const float*)d_in[12];
    const float* fcT1_b2 = (const float*)d_in[13];
    const float* fcT2_W1 = (const float*)d_in[14];
    const float* fcT2_b1 = (const float*)d_in[15];
    const float* fcT2_W2 = (const float*)d_in[16];
    const float* fcT2_b2 = (const float*)d_in[17];

    cudaFuncSetAttribute(mlp_kernel, cudaFuncAttributeMaxDynamicSharedMemorySize,
                         SMEM_B_BYTES);

    prep_kernel<<<NSS, 256>>>(xc, fc_W1, fc_b1, fc_W2, fc_b2,
                              fcR_W1, fcR_b1, fcR_W2, fcR_b2,
                              fcT1_W1, fcT1_b1, fcT2_W1, fcT2_b1);

    dim3 gB((NTT + TCHUNK - 1)/TCHUNK, (NSS + 31)/32);
    mlp_kernel<<<gB, 256, SMEM_B_BYTES>>>(x, fcT1_W1, fcT2_W1,
                                          fcT1_W2, fcT1_b2, fcT2_W2, fcT2_b2);

    scan_kernel<<<(NSH + 127)/128, 128>>>();

    dim3 gC((NTT + CTT - 1)/CTT, NSS);
    conv_kernel<<<gC, 128>>>((float*)d_out);
}